// round 11
// baseline (speedup 1.0000x reference)
#include <cuda_runtime.h>
#include <cstdint>
#include <cub/cub.cuh>

#define NUM_A 9
#define HH 128
#define WW 128
#define NBOX (NUM_A * HH * WW)   /* 147456 */
#define KTOP 6000
#define NPOST 300
#define NWIN 188                 /* ceil(6000/32) */
#define PADK 6016
#define PADC 6016
#define PT 256
#define FULLM 0xFFFFFFFFu

__constant__ float c_sizes[NUM_A] = {4.f, 8.f, 12.f, 16.f, 24.f, 32.f, 48.f, 64.f, 96.f};

__device__ unsigned g_sk_a[NBOX], g_sk_b[NBOX], g_sv_a[NBOX], g_sv_b[NBOX];
__device__ unsigned g_yk_a[KTOP], g_yk_b[KTOP], g_yv_a[KTOP], g_yv_b[KTOP];
__device__ float4 g_props[KTOP];
__device__ __align__(256) unsigned char g_cub_temp[32u * 1024u * 1024u];
__device__ float4   g_box[PADK];
__device__ float    g_area[PADK];
__device__ int      g_J1[PADK];
__device__ unsigned g_BMT[NWIN * PADC];   /* ~4.3MB kill bitmap, victim-word major */

// ---------------- decode (bit-exact vs reference) ----------------
__device__ __forceinline__ float4 decode_box(int idx, const float4* __restrict__ deltas,
                                             bool* keep)
{
    int a   = idx / (HH * WW);
    int rem = idx - a * (HH * WW);
    int h   = rem >> 7;
    int w   = rem & 127;
    float s    = c_sizes[a];
    float half = s * 0.5f;
    float ax = ((float)h + 0.5f) - half;
    float ay = ((float)w + 0.5f) - half;
    float4 d = deltas[idx];
    float x1 = fmaxf(ax + d.x, 0.0f);
    float y1 = fmaxf(ay + d.y, 0.0f);
    float bw = fmaxf(s + d.z, 0.0f);
    float bh = fmaxf(s + d.w, 0.0f);
    float x2 = x1 + bw;
    float y2 = y1 + bh;
    x1 = fminf(x1, 128.0f);
    y1 = fminf(y1, 128.0f);
    x2 = fminf(x2, 128.0f);
    y2 = fminf(y2, 128.0f);
    float ow = x2 - x1;
    float oh = y2 - y1;
    *keep = (ow >= 3.0f) && (oh >= 3.0f);
    return make_float4(x1, y1, ow, oh);
}

// exact: rn(n/ar) >= 0.7f, division-free common path
__device__ __forceinline__ bool iou_ge(float n, float ar)
{
    float t = fmaf(-0.7f, ar, n);
    if (t >= 0.0f) return true;
    if (t <= -3.2e-8f * ar) return false;
    return __fdiv_rn(n, ar) >= 0.7f;
}

__global__ void k_score(const float* __restrict__ scores, const float4* __restrict__ deltas)
{
    int i = blockIdx.x * blockDim.x + threadIdx.x;
    if (i >= NBOX) return;
    bool keep;
    (void)decode_box(i, deltas, &keep);
    float sc = keep ? scores[i] : __int_as_float(0xFF800000);
    unsigned u   = __float_as_uint(sc);
    unsigned asc = u ^ ((unsigned)((int)u >> 31) | 0x80000000u);
    g_sk_a[i] = ~asc;
    g_sv_a[i] = (unsigned)i;
}

__global__ void k_props(const float4* __restrict__ deltas)
{
    int r = blockIdx.x * blockDim.x + threadIdx.x;
    if (r >= KTOP) return;
    int idx = (int)g_sv_b[r];
    bool keep;
    float4 p = decode_box(idx, deltas, &keep);
    g_props[r] = p;
    float y2 = p.y + p.w;
    g_yk_a[r] = ~__float_as_uint(y2);
    g_yv_a[r] = (unsigned)r;
}

__global__ void k_zero()
{
    int i = blockIdx.x * blockDim.x + threadIdx.x;
    if (i < NWIN * PADC) g_BMT[i] = 0u;
}

// boxes in y2-order, areas, exact J1 band bound
__global__ void k_prep()
{
    int m = blockIdx.x * blockDim.x + threadIdx.x;
    if (m >= PADK) return;
    if (m < KTOP) {
        float4 p = g_props[(int)g_yv_b[m]];
        float x1 = p.x, y1 = p.y, x2 = p.x + p.z, y2 = p.y + p.w;
        g_box[m]  = make_float4(x1, y1, x2, y2);
        g_area[m] = fmaxf((x2 - x1) * (y2 - y1), 1e-6f);
        // first j>m with fl(y2_j - y1_m) <= -1 -> ih_fl <= 0 beyond (exact, monotone)
        int lo = m + 1, hi = KTOP;
        while (lo < hi) {
            int mid = (lo + hi) >> 1;
            float y2j = __uint_as_float(~g_yk_b[mid]);
            if (__fadd_rn(y2j, -y1) <= -1.0f) hi = mid; else lo = mid + 1;
        }
        g_J1[m] = lo;
    } else {
        g_box[m] = make_float4(0.f, 0.f, 0.f, 0.f);
        g_area[m] = 1.f;
        g_J1[m] = 0;
    }
}

// pair enumeration: CTA owns 32 i's; tiles j-band through shared; fills BMT
__global__ void __launch_bounds__(256) void_guard();  // (no-op decl to keep nvcc happy if unused)
__global__ void __launch_bounds__(256) k_pairs()
{
    __shared__ float4 tb[PT];
    __shared__ float  ta[PT];
    __shared__ int sMax;
    int tid = threadIdx.x;
    int i0  = blockIdx.x * 32;
    int il  = tid >> 3, ck = tid & 7;
    int i   = i0 + il;
    bool iok = (i < KTOP);
    float4 bi = iok ? g_box[i] : make_float4(0.f, 0.f, 0.f, 0.f);
    float  ai = iok ? g_area[i] : 1.f;
    int   J1i = iok ? g_J1[i] : 0;
    if (tid == 0) sMax = 0;
    __syncthreads();
    if (ck == 0 && iok) atomicMax(&sMax, J1i);
    __syncthreads();
    int jend = sMax;
    int t0 = (i0 + 1) & ~31;
    for (int t = t0; t < jend; t += PT) {
        __syncthreads();
        {
            int idx = t + tid;
            if (idx < PADK) { tb[tid] = g_box[idx]; ta[tid] = g_area[idx]; }
            else            { tb[tid] = make_float4(0.f,0.f,0.f,0.f); ta[tid] = 1.f; }
        }
        __syncthreads();
        if (!iok) continue;
        int jbase = t + (ck << 5);
        unsigned fwd = 0;
        for (int b = 0; b < 32; ++b) {
            int j = jbase + b;
            if (j <= i || j >= J1i) continue;
            float4 bj = tb[(ck << 5) + b];
            float iw = fminf(bi.z, bj.z) - fmaxf(bi.x, bj.x) + 1.0f;
            if (iw <= 0.0f) continue;
            float ih = fminf(bi.w, bj.w) - fmaxf(bi.y, bj.y) + 1.0f;
            if (ih <= 0.0f) continue;
            float inter = iw * ih;
            if (iou_ge(inter, ta[(ck << 5) + b])) fwd |= 1u << b;  // i kills j
            if (iou_ge(inter, ai))                                  // j kills i
                atomicOr(&g_BMT[(unsigned)(i >> 5) * PADC + j], 1u << (i & 31));
        }
        if (fwd) atomicOr(&g_BMT[(unsigned)(jbase >> 5) * PADC + i], fwd);
    }
}

// serial chain: pure bitops, prefetched BMT columns, 2 barriers/window
__global__ void __launch_bounds__(1024, 1) k_serial(float* __restrict__ out)
{
    __shared__ unsigned valid[NWIN];
    __shared__ unsigned s_exec;
    __shared__ int ssc[1024];
    const int tid  = threadIdx.x;
    const int lane = tid & 31;
    const int wid  = tid >> 5;

    for (int i = tid; i < NPOST * 4; i += 1024) out[i] = 0.0f;
    if (tid < NWIN) valid[tid] = (tid == NWIN - 1) ? 0x0000FFFFu : FULLM;

    unsigned cur[7], nxt[7];
    if (wid == 31) {
        nxt[0] = g_BMT[0 * PADC + lane];            // u=0, c=lane (window 0)
    } else {
#pragma unroll
        for (int k = 0; k < 7; ++k) {
            int u = wid + 31 * k;
            nxt[k] = (u < NWIN) ? g_BMT[(unsigned)u * PADC + lane] : 0u;
        }
    }

    for (int w = 0; w < NWIN; ++w) {
        __syncthreads();                            // A: prior applies visible
        unsigned vm = valid[w];
#pragma unroll
        for (int k = 0; k < 7; ++k) cur[k] = nxt[k];
        int wn = w + 1;
        if (wn < NWIN) {                            // prefetch next window's columns
            unsigned cbase = (unsigned)(wn << 5) + lane;
            if (wid == 31) {
                nxt[0] = g_BMT[(unsigned)wn * PADC + cbase];
            } else {
#pragma unroll
                for (int k = 0; k < 7; ++k) {
                    int u = wid + 31 * k;
                    nxt[k] = (u < NWIN) ? g_BMT[(unsigned)u * PADC + cbase] : 0u;
                }
            }
        }
        if (vm == 0) continue;                      // uniform

        if (wid == 31) {
            // forward-only row for chain resolve
            unsigned row = (lane < 31) ? (cur[0] & (0xFFFFFFFEu << lane)) : 0u;
            unsigned exec;
            if (__ballot_sync(FULLM, row != 0u) == 0u) {
                exec = vm;                          // no intra-window edges
            } else {
                unsigned rem = 0; exec = 0;
#pragma unroll
                for (int l = 0; l < 32; ++l) {
                    unsigned rl = __shfl_sync(FULLM, row, l);
                    unsigned b = 1u << l;
                    if ((vm & b) && !(rem & b)) { exec |= b; rem |= rl; }
                }
            }
            if (lane == 0) s_exec = exec;
        }
        __syncthreads();                            // B: exec published

        if (wid < 31) {
            unsigned exec = s_exec;
#pragma unroll
            for (int k = 0; k < 7; ++k) {
                unsigned d = ((exec >> lane) & 1u) ? cur[k] : 0u;
#pragma unroll
                for (int o = 16; o; o >>= 1) d |= __shfl_xor_sync(FULLM, d, o);
                int u = wid + 31 * k;
                if (lane == 0 && u < NWIN && d) valid[u] &= ~d;
            }
        }
    }
    __syncthreads();

    // output: first NPOST survivors in y-order
    int c = (tid < NWIN) ? __popc(valid[tid]) : 0;
    ssc[tid] = c;
    __syncthreads();
    for (int off = 1; off < 1024; off <<= 1) {
        int add = (tid >= off) ? ssc[tid - off] : 0;
        __syncthreads();
        ssc[tid] += add;
        __syncthreads();
    }
    if (tid < NWIN) {
        int pos = ssc[tid] - c;
        unsigned v = valid[tid];
        while (v) {
            int b = __ffs(v) - 1; v &= v - 1;
            if (pos < NPOST) {
                int m = (tid << 5) + b;
                float4 p = g_props[(int)g_yv_b[m]];
                out[pos * 4 + 0] = p.x;
                out[pos * 4 + 1] = p.y;
                out[pos * 4 + 2] = p.z;
                out[pos * 4 + 3] = p.w;
            }
            ++pos;
        }
    }
}

extern "C" void kernel_launch(void* const* d_in, const int* in_sizes, int n_in,
                              void* d_out, int out_size)
{
    const float*  scores = (const float*)d_in[0];
    const float4* deltas = (const float4*)d_in[1];
    float* out = (float*)d_out;
    (void)in_sizes; (void)n_in; (void)out_size;

    void *p_ska, *p_skb, *p_sva, *p_svb, *p_yka, *p_ykb, *p_yva, *p_yvb, *p_tmp;
    cudaGetSymbolAddress(&p_ska, g_sk_a);
    cudaGetSymbolAddress(&p_skb, g_sk_b);
    cudaGetSymbolAddress(&p_sva, g_sv_a);
    cudaGetSymbolAddress(&p_svb, g_sv_b);
    cudaGetSymbolAddress(&p_yka, g_yk_a);
    cudaGetSymbolAddress(&p_ykb, g_yk_b);
    cudaGetSymbolAddress(&p_yva, g_yv_a);
    cudaGetSymbolAddress(&p_yvb, g_yv_b);
    cudaGetSymbolAddress(&p_tmp, g_cub_temp);

    k_zero<<<(NWIN * PADC + 1023) / 1024, 1024>>>();
    k_score<<<(NBOX + 255) / 256, 256>>>(scores, deltas);

    size_t tb = sizeof(g_cub_temp);
    cub::DeviceRadixSort::SortPairs(p_tmp, tb,
        (const unsigned*)p_ska, (unsigned*)p_skb,
        (const unsigned*)p_sva, (unsigned*)p_svb, NBOX);

    k_props<<<(KTOP + 255) / 256, 256>>>(deltas);

    tb = sizeof(g_cub_temp);
    cub::DeviceRadixSort::SortPairs(p_tmp, tb,
        (const unsigned*)p_yka, (unsigned*)p_ykb,
        (const unsigned*)p_yva, (unsigned*)p_yvb, KTOP);

    k_prep<<<(PADK + 255) / 256, 256>>>();
    k_pairs<<<NWIN, 256>>>();
    k_serial<<<1, 1024>>>(out);
}

// round 12
// speedup vs baseline: 1.0207x; 1.0207x over previous
#include <cuda_runtime.h>
#include <cstdint>
#include <cub/cub.cuh>

#define NUM_A 9
#define HH 128
#define WW 128
#define NBOX (NUM_A * HH * WW)   /* 147456 */
#define KTOP 6000
#define NPOST 300
#define NWIN 188                 /* ceil(6000/32) */
#define PADK 6016
#define ROWW 192                 /* padded row stride (words) */
#define PT 256
#define FULLM 0xFFFFFFFFu

__constant__ float c_sizes[NUM_A] = {4.f, 8.f, 12.f, 16.f, 24.f, 32.f, 48.f, 64.f, 96.f};

__device__ unsigned g_sk_a[NBOX], g_sk_b[NBOX], g_sv_a[NBOX], g_sv_b[NBOX];
__device__ unsigned g_yk_a[KTOP], g_yk_b[KTOP], g_yv_a[KTOP], g_yv_b[KTOP];
__device__ float4 g_props[KTOP];
__device__ __align__(256) unsigned char g_cub_temp[32u * 1024u * 1024u];
__device__ float4   g_box[PADK];
__device__ float    g_area[PADK];
__device__ int      g_J1[PADK];
__device__ unsigned g_K[PADK * ROWW];    /* candidate-major kill rows (~4.6MB) */
__device__ int      g_rowLo[PADK], g_rowHi[PADK];
__device__ unsigned g_killerm[NWIN];

// ---------------- decode (bit-exact vs reference) ----------------
__device__ __forceinline__ float4 decode_box(int idx, const float4* __restrict__ deltas,
                                             bool* keep)
{
    int a   = idx / (HH * WW);
    int rem = idx - a * (HH * WW);
    int h   = rem >> 7;
    int w   = rem & 127;
    float s    = c_sizes[a];
    float half = s * 0.5f;
    float ax = ((float)h + 0.5f) - half;
    float ay = ((float)w + 0.5f) - half;
    float4 d = deltas[idx];
    float x1 = fmaxf(ax + d.x, 0.0f);
    float y1 = fmaxf(ay + d.y, 0.0f);
    float bw = fmaxf(s + d.z, 0.0f);
    float bh = fmaxf(s + d.w, 0.0f);
    float x2 = x1 + bw;
    float y2 = y1 + bh;
    x1 = fminf(x1, 128.0f);
    y1 = fminf(y1, 128.0f);
    x2 = fminf(x2, 128.0f);
    y2 = fminf(y2, 128.0f);
    float ow = x2 - x1;
    float oh = y2 - y1;
    *keep = (ow >= 3.0f) && (oh >= 3.0f);
    return make_float4(x1, y1, ow, oh);
}

// exact: rn(n/ar) >= 0.7f, division-free common path
__device__ __forceinline__ bool iou_ge(float n, float ar)
{
    float t = fmaf(-0.7f, ar, n);
    if (t >= 0.0f) return true;
    if (t <= -3.2e-8f * ar) return false;
    return __fdiv_rn(n, ar) >= 0.7f;
}

__global__ void k_score(const float* __restrict__ scores, const float4* __restrict__ deltas)
{
    int i = blockIdx.x * blockDim.x + threadIdx.x;
    if (i >= NBOX) return;
    bool keep;
    (void)decode_box(i, deltas, &keep);
    float sc = keep ? scores[i] : __int_as_float(0xFF800000);
    unsigned u   = __float_as_uint(sc);
    unsigned asc = u ^ ((unsigned)((int)u >> 31) | 0x80000000u);
    g_sk_a[i] = ~asc;
    g_sv_a[i] = (unsigned)i;
}

__global__ void k_props(const float4* __restrict__ deltas)
{
    int r = blockIdx.x * blockDim.x + threadIdx.x;
    if (r >= KTOP) return;
    int idx = (int)g_sv_b[r];
    bool keep;
    float4 p = decode_box(idx, deltas, &keep);
    g_props[r] = p;
    float y2 = p.y + p.w;
    g_yk_a[r] = ~__float_as_uint(y2);
    g_yv_a[r] = (unsigned)r;
}

__global__ void k_zero()
{
    int i = blockIdx.x * blockDim.x + threadIdx.x;
    if (i < PADK * ROWW) g_K[i] = 0u;
}

// boxes in y2-order, areas, exact J1 band bound
__global__ void k_prep()
{
    int m = blockIdx.x * blockDim.x + threadIdx.x;
    if (m >= PADK) return;
    if (m < KTOP) {
        float4 p = g_props[(int)g_yv_b[m]];
        float x1 = p.x, y1 = p.y, x2 = p.x + p.z, y2 = p.y + p.w;
        g_box[m]  = make_float4(x1, y1, x2, y2);
        g_area[m] = fmaxf((x2 - x1) * (y2 - y1), 1e-6f);
        // first j>m with fl(y2_j - y1_m) <= -1 -> ih <= 0 beyond (exact, monotone)
        int lo = m + 1, hi = KTOP;
        while (lo < hi) {
            int mid = (lo + hi) >> 1;
            float y2j = __uint_as_float(~g_yk_b[mid]);
            if (__fadd_rn(y2j, -y1) <= -1.0f) hi = mid; else lo = mid + 1;
        }
        g_J1[m] = lo;
    } else {
        g_box[m] = make_float4(0.f, 0.f, 0.f, 0.f);
        g_area[m] = 1.f;
        g_J1[m] = 0;
    }
}

// pair enumeration: CTA owns 32 i's; tiles j-band through shared; fills g_K rows
__global__ void __launch_bounds__(256) k_pairs()
{
    __shared__ float4 tb[PT];
    __shared__ float  ta[PT];
    __shared__ int sMax;
    int tid = threadIdx.x;
    int i0  = blockIdx.x * 32;
    int il  = tid >> 3, ck = tid & 7;
    int i   = i0 + il;
    bool iok = (i < KTOP);
    float4 bi = iok ? g_box[i] : make_float4(0.f, 0.f, 0.f, 0.f);
    float  ai = iok ? g_area[i] : 1.f;
    int   J1i = iok ? g_J1[i] : 0;
    if (tid == 0) sMax = 0;
    __syncthreads();
    if (ck == 0 && iok) atomicMax(&sMax, J1i);
    __syncthreads();
    int jend = sMax;
    int t0 = (i0 + 1) & ~31;
    for (int t = t0; t < jend; t += PT) {
        __syncthreads();
        {
            int idx = t + tid;
            if (idx < PADK) { tb[tid] = g_box[idx]; ta[tid] = g_area[idx]; }
            else            { tb[tid] = make_float4(0.f,0.f,0.f,0.f); ta[tid] = 1.f; }
        }
        __syncthreads();
        if (!iok) continue;
        int jbase = t + (ck << 5);
        unsigned fwd = 0;
        for (int b = 0; b < 32; ++b) {
            int j = jbase + b;
            if (j <= i || j >= J1i) continue;
            float4 bj = tb[(ck << 5) + b];
            float iw = fminf(bi.z, bj.z) - fmaxf(bi.x, bj.x) + 1.0f;
            if (iw <= 0.0f) continue;
            float ih = fminf(bi.w, bj.w) - fmaxf(bi.y, bj.y) + 1.0f;
            if (ih <= 0.0f) continue;
            float inter = iw * ih;
            if (iou_ge(inter, ta[(ck << 5) + b])) fwd |= 1u << b;   // i kills j
            if (iou_ge(inter, ai))                                   // j kills i
                atomicOr(&g_K[(unsigned)j * ROWW + (i >> 5)], 1u << (i & 31));
        }
        if (fwd) atomicOr(&g_K[(unsigned)i * ROWW + (jbase >> 5)], fwd);
    }
}

// per-candidate nonzero word range + per-window killer bitmap
__global__ void k_meta()   /* <<<NWIN, 32>>> */
{
    int c = blockIdx.x * 32 + threadIdx.x;    // c < PADK exactly
    const unsigned* rp = &g_K[(unsigned)c * ROWW];
    int lo = NWIN, hi = -1;
#pragma unroll 4
    for (int u = 0; u < NWIN; ++u) {
        unsigned v = rp[u];
        if (v) { if (u < lo) lo = u; hi = u; }
    }
    g_rowLo[c] = lo;
    g_rowHi[c] = hi;
    unsigned kb = __ballot_sync(FULLM, hi >= 0);
    if (threadIdx.x == 0) g_killerm[blockIdx.x] = kb;
}

// serial chain: skip killer-free windows; apply only exec'd killers' rows
__global__ void __launch_bounds__(1024, 1) k_serial(float* __restrict__ out)
{
    __shared__ unsigned valid[NWIN];
    __shared__ unsigned killerm[NWIN];
    __shared__ int sLoC[32], sHiC[32], sLoN[32], sHiN[32];
    __shared__ unsigned s_exec;
    __shared__ int ssc[1024];
    const int tid  = threadIdx.x;
    const int lane = tid & 31;
    const int wid  = tid >> 5;

    for (int i = tid; i < NPOST * 4; i += 1024) out[i] = 0.0f;
    if (tid < NWIN) {
        valid[tid]   = (tid == NWIN - 1) ? 0x0000FFFFu : FULLM;
        killerm[tid] = g_killerm[tid];
    }
    unsigned row_nxt = 0;
    if (wid == 31) {                      // prefetch window 0 metadata
        row_nxt = g_K[(unsigned)lane * ROWW + 0];
        sLoN[lane] = g_rowLo[lane];
        sHiN[lane] = g_rowHi[lane];
    }
    __syncthreads();

    for (int w = 0; w < NWIN; ++w) {
        __syncthreads();                  // A: prior applies visible
        unsigned row_cur = 0;
        if (wid == 31) {                  // rotate + prefetch w+1 (warp-internal ordering)
            row_cur = row_nxt;
            int lo = sLoN[lane], hi = sHiN[lane];
            sLoC[lane] = lo; sHiC[lane] = hi;
            int wn = w + 1;
            if (wn < NWIN) {
                int c = (wn << 5) + lane;
                row_nxt = g_K[(unsigned)c * ROWW + wn];
                sLoN[lane] = g_rowLo[c];
                sHiN[lane] = g_rowHi[c];
            }
        }
        unsigned vm = valid[w];
        unsigned km = vm & killerm[w];
        if (km == 0) continue;            // uniform: no valid killers -> no effects

        if (wid == 31) {
            // forward-masked intra-window row for chain resolve
            unsigned rowf = (lane < 31) ? (row_cur & (0xFFFFFFFEu << lane)) : 0u;
            unsigned execK;
            if (__ballot_sync(FULLM, rowf != 0u) == 0u) {
                execK = km;
            } else {
                unsigned rem = 0; execK = 0;
#pragma unroll
                for (int l = 0; l < 32; ++l) {
                    unsigned rl = __shfl_sync(FULLM, rowf, l);
                    unsigned b = 1u << l;
                    if ((km & b) && !(rem & b)) { execK |= b; rem |= rl; }
                }
            }
            if (lane == 0) s_exec = execK;
        }
        __syncthreads();                  // B: exec published

        if (wid < 31) {
            unsigned e = s_exec;
            int idx = 0;
            while (e) {
                int l = __ffs(e) - 1; e &= e - 1;
                if ((idx % 31) == wid) {
                    int c = (w << 5) + l;
                    int lo = sLoC[l], hi = sHiC[l];
                    const unsigned* rp = &g_K[(unsigned)c * ROWW];
                    for (int u = lo + lane; u <= hi; u += 32) {
                        unsigned d = rp[u];
                        if (d) atomicAnd(&valid[u], ~d);
                    }
                }
                ++idx;
            }
        }
    }
    __syncthreads();

    // output: first NPOST survivors in y-order
    int c = (tid < NWIN) ? __popc(valid[tid]) : 0;
    ssc[tid] = c;
    __syncthreads();
    for (int off = 1; off < 1024; off <<= 1) {
        int add = (tid >= off) ? ssc[tid - off] : 0;
        __syncthreads();
        ssc[tid] += add;
        __syncthreads();
    }
    if (tid < NWIN) {
        int pos = ssc[tid] - c;
        unsigned v = valid[tid];
        while (v) {
            int b = __ffs(v) - 1; v &= v - 1;
            if (pos < NPOST) {
                int m = (tid << 5) + b;
                float4 p = g_props[(int)g_yv_b[m]];
                out[pos * 4 + 0] = p.x;
                out[pos * 4 + 1] = p.y;
                out[pos * 4 + 2] = p.z;
                out[pos * 4 + 3] = p.w;
            }
            ++pos;
        }
    }
}

extern "C" void kernel_launch(void* const* d_in, const int* in_sizes, int n_in,
                              void* d_out, int out_size)
{
    const float*  scores = (const float*)d_in[0];
    const float4* deltas = (const float4*)d_in[1];
    float* out = (float*)d_out;
    (void)in_sizes; (void)n_in; (void)out_size;

    void *p_ska, *p_skb, *p_sva, *p_svb, *p_yka, *p_ykb, *p_yva, *p_yvb, *p_tmp;
    cudaGetSymbolAddress(&p_ska, g_sk_a);
    cudaGetSymbolAddress(&p_skb, g_sk_b);
    cudaGetSymbolAddress(&p_sva, g_sv_a);
    cudaGetSymbolAddress(&p_svb, g_sv_b);
    cudaGetSymbolAddress(&p_yka, g_yk_a);
    cudaGetSymbolAddress(&p_ykb, g_yk_b);
    cudaGetSymbolAddress(&p_yva, g_yv_a);
    cudaGetSymbolAddress(&p_yvb, g_yv_b);
    cudaGetSymbolAddress(&p_tmp, g_cub_temp);

    k_zero<<<(PADK * ROWW + 1023) / 1024, 1024>>>();
    k_score<<<(NBOX + 255) / 256, 256>>>(scores, deltas);

    size_t tb = sizeof(g_cub_temp);
    cub::DeviceRadixSort::SortPairs(p_tmp, tb,
        (const unsigned*)p_ska, (unsigned*)p_skb,
        (const unsigned*)p_sva, (unsigned*)p_svb, NBOX);

    k_props<<<(KTOP + 255) / 256, 256>>>(deltas);

    tb = sizeof(g_cub_temp);
    cub::DeviceRadixSort::SortPairs(p_tmp, tb,
        (const unsigned*)p_yka, (unsigned*)p_ykb,
        (const unsigned*)p_yva, (unsigned*)p_yvb, KTOP);

    k_prep<<<(PADK + 255) / 256, 256>>>();
    k_pairs<<<NWIN, 256>>>();
    k_meta<<<NWIN, 32>>>();
    k_serial<<<1, 1024>>>(out);
}

// round 13
// speedup vs baseline: 2.6519x; 2.5980x over previous
#include <cuda_runtime.h>
#include <cstdint>
#include <cub/cub.cuh>

#define NUM_A 9
#define HH 128
#define WW 128
#define NBOX (NUM_A * HH * WW)   /* 147456 */
#define KTOP 6000
#define NPOST 300
#define NMS_NT 1024
#define OWN 6                    /* 1024*6 = 6144 >= 6000 */
#define NWORDS 188               /* ceil(6000/32) */
#define WIN 32
#define FULLM 0xFFFFFFFFu

__constant__ float c_sizes[NUM_A] = {4.f, 8.f, 12.f, 16.f, 24.f, 32.f, 48.f, 64.f, 96.f};

__device__ unsigned g_sk_a[NBOX], g_sk_b[NBOX], g_sv_a[NBOX], g_sv_b[NBOX];
__device__ unsigned g_yk_a[KTOP], g_yk_b[KTOP], g_yv_a[KTOP], g_yv_b[KTOP];
__device__ float4 g_props[KTOP];
__device__ __align__(256) unsigned char g_cub_temp[32u * 1024u * 1024u];

// ---------------- decode (bit-exact vs reference) ----------------
__device__ __forceinline__ float4 decode_box(int idx, const float4* __restrict__ deltas,
                                             bool* keep)
{
    int a   = idx / (HH * WW);
    int rem = idx - a * (HH * WW);
    int h   = rem >> 7;
    int w   = rem & 127;
    float s    = c_sizes[a];
    float half = s * 0.5f;
    float ax = ((float)h + 0.5f) - half;
    float ay = ((float)w + 0.5f) - half;
    float4 d = deltas[idx];
    float x1 = fmaxf(ax + d.x, 0.0f);
    float y1 = fmaxf(ay + d.y, 0.0f);
    float bw = fmaxf(s + d.z, 0.0f);
    float bh = fmaxf(s + d.w, 0.0f);
    float x2 = x1 + bw;
    float y2 = y1 + bh;
    x1 = fminf(x1, 128.0f);
    y1 = fminf(y1, 128.0f);
    x2 = fminf(x2, 128.0f);
    y2 = fminf(y2, 128.0f);
    float ow = x2 - x1;
    float oh = y2 - y1;
    *keep = (ow >= 3.0f) && (oh >= 3.0f);
    return make_float4(x1, y1, ow, oh);
}

// exact: rn(n/ar) >= 0.7f, division-free common path
__device__ __forceinline__ bool iou_ge(float n, float ar)
{
    float t = fmaf(-0.7f, ar, n);
    if (t >= 0.0f) return true;                 // e >= -2^-150 -> suppress
    if (t <= -3.2e-8f * ar) return false;       // e <= -2^-25*ar -> no
    return __fdiv_rn(n, ar) >= 0.7f;            // rare exact fallback
}

__global__ void k_score(const float* __restrict__ scores, const float4* __restrict__ deltas)
{
    int i = blockIdx.x * blockDim.x + threadIdx.x;
    if (i >= NBOX) return;
    bool keep;
    (void)decode_box(i, deltas, &keep);
    float sc = keep ? scores[i] : __int_as_float(0xFF800000);
    unsigned u   = __float_as_uint(sc);
    unsigned asc = u ^ ((unsigned)((int)u >> 31) | 0x80000000u);
    g_sk_a[i] = ~asc;
    g_sv_a[i] = (unsigned)i;
}

__global__ void k_props(const float4* __restrict__ deltas)
{
    int r = blockIdx.x * blockDim.x + threadIdx.x;
    if (r >= KTOP) return;
    int idx = (int)g_sv_b[r];
    bool keep;
    float4 p = decode_box(idx, deltas, &keep);
    g_props[r] = p;
    float y2 = p.y + p.w;
    g_yk_a[r] = ~__float_as_uint(y2);
    g_yv_a[r] = (unsigned)r;
}

// ---------------- NMS ----------------
struct SmemNMS {
    float4   sbox[KTOP];       // (x1,y1,x2,y2) y2-desc sorted
    unsigned swords[NWORDS];   // validity bitmask
    int      T[132];           // T[k] = first m with y2[m] <= k
    int      s_nc;
    int      scidx[WIN];
    float4   scbox[WIN];
    int      sJ1c[WIN];
    unsigned srow[WIN];
    int      ssc[NMS_NT];
};

__global__ void __launch_bounds__(NMS_NT, 1) k_nms(float* __restrict__ out)
{
    extern __shared__ char sm_raw[];
    SmemNMS* s = (SmemNMS*)sm_raw;

    const int tid  = threadIdx.x;
    const int lane = tid & 31;
    const int wid  = tid >> 5;

    for (int i = tid; i < NPOST * 4; i += NMS_NT) out[i] = 0.0f;

    // boxes in y2-sorted order
    for (int m = tid; m < KTOP; m += NMS_NT) {
        float4 p = g_props[(int)g_yv_b[m]];
        s->sbox[m] = make_float4(p.x, p.y, p.x + p.z, p.y + p.w);
    }
    if (tid < NWORDS) s->swords[tid] = (tid == NWORDS - 1) ? 0x0000FFFFu : FULLM;
    __syncthreads();

    // T table (first index with y2 <= k; y2 in [0,130))
    if (tid < 132) {
        float v = (float)tid;
        int lo = 0, hi = KTOP;
        while (lo < hi) { int mid = (lo + hi) >> 1; if (s->sbox[mid].w > v) lo = mid + 1; else hi = mid; }
        s->T[tid] = lo;
    }

    // owned boxes in registers
    const int base = tid * OWN;
    float rx1[OWN], ry1[OWN], rx2[OWN], ry2[OWN], rar[OWN];
    unsigned rv = 0;
    float my_ymin1 = 1e30f;
#pragma unroll
    for (int q = 0; q < OWN; ++q) {
        int j = base + q;
        if (j < KTOP) {
            float4 b = s->sbox[j];
            rx1[q] = b.x; ry1[q] = b.y; rx2[q] = b.z; ry2[q] = b.w;
            rar[q] = fmaxf((b.z - b.x) * (b.w - b.y), 1e-6f);
            rv |= 1u << q;
            my_ymin1 = fminf(my_ymin1, b.y);
        } else {
            rx1[q] = 0.f; ry1[q] = 0.f; rx2[q] = 0.f; ry2[q] = 0.f; rar[q] = 1.f;
        }
    }
    // warp-level min y1 (for candidate pruning ballots)
    float wmin_y1 = my_ymin1;
#pragma unroll
    for (int o = 16; o; o >>= 1) wmin_y1 = fminf(wmin_y1, __shfl_xor_sync(FULLM, wmin_y1, o));
    const int warp_first_box = (wid << 5) * OWN;
    __syncthreads();

    int p = 0;  // gather cursor (warp 0 register)

    for (;;) {
        // ---- phase 0: warp 0 gathers next WIN valid candidates ----
        if (wid == 0) {
            int nc = 0;
            while (nc < WIN && p < KTOP) {
                int w0 = p >> 5;
                int widx = w0 + lane;
                unsigned w = (widx < NWORDS) ? s->swords[widx] : 0u;
                if (lane == 0) w &= (FULLM << (p & 31));
                int cnt = __popc(w);
                int pre = cnt;
#pragma unroll
                for (int o = 1; o < 32; o <<= 1) {
                    int v = __shfl_up_sync(FULLM, pre, o);
                    if (lane >= o) pre += v;
                }
                int total = __shfl_sync(FULLM, pre, 31);
                int r = nc + (pre - cnt);
                unsigned ww = w;
                while (ww && r < WIN) {
                    int b = __ffs(ww) - 1; ww &= ww - 1;
                    s->scidx[r] = (widx << 5) + b;
                    ++r;
                }
                nc += total; if (nc > WIN) nc = WIN;
                p = (w0 + 32) << 5;
                if (p > KTOP) p = KTOP;
                __syncwarp();
                if (nc == WIN) p = s->scidx[WIN - 1] + 1;
            }
            if (lane < nc) {
                int c = s->scidx[lane];
                float4 b = s->sbox[c];
                s->scbox[lane] = b;
                float thr = b.y - 1.001f;
                int j1;
                if (thr < 0.0f) j1 = KTOP;
                else { int kk = (int)thr; if (kk > 131) kk = 131; j1 = s->T[kk]; }
                s->sJ1c[lane] = j1;
            } else {
                s->scbox[lane] = make_float4(1e30f, 1e30f, -1e30f, -1e30f);
                s->sJ1c[lane] = 0;
                s->scidx[lane] = 0x7FFFFFFF;
            }
            if (lane == 0) s->s_nc = nc;
        }
        __syncthreads();                       // B: candidates published
        int nc = s->s_nc;
        if (nc == 0) break;
        unsigned ncm = (nc >= 32) ? FULLM : ((1u << nc) - 1u);

        // ---- phase 1: warp `wid` computes forward row `wid` (one ballot) ----
        {
            float4 cw = s->scbox[wid];
            float4 cj = s->scbox[lane];
            int ok = 0;
            if (lane > wid) {
                float arj = fmaxf((cj.z - cj.x) * (cj.w - cj.y), 1e-6f);
                float iw = fminf(cw.z, cj.z) - fmaxf(cw.x, cj.x) + 1.0f;
                float ih = fminf(cw.w, cj.w) - fmaxf(cw.y, cj.y) + 1.0f;
                if (iw > 0.0f && ih > 0.0f && iou_ge(iw * ih, arj)) ok = 1;
            }
            unsigned rm = __ballot_sync(FULLM, ok) & ncm;
            if (lane == 0) s->srow[wid] = rm;
        }
        __syncthreads();                       // C: rows published

        // ---- phase 2: chain (redundant, register-only) + pruned apply ----
        unsigned row = s->srow[lane];          // one LDS per lane
        // per-warp candidate pruning ballots (1 LDS.128 + 1 LDS each)
        float cy2l = s->scbox[lane].w;
        int   j1l  = s->sJ1c[lane];
        unsigned ymask = __ballot_sync(FULLM, cy2l + 1.0001f > wmin_y1);
        unsigned amask = __ballot_sync(FULLM, j1l > warp_first_box);

        unsigned rem = 0, exec = 0;
#pragma unroll
        for (int l = 0; l < 32; ++l) {
            unsigned rl = __shfl_sync(FULLM, row, l);
            unsigned b = 1u << l;
            if ((ncm & b) && !(rem & b)) { exec |= b; rem |= rl; }
        }

        if (rv) {
            unsigned oldrv = rv;
            unsigned e = exec & ymask & amask;
            while (e) {
                int m = __ffs(e) - 1; e &= e - 1;
                int qlim = s->sJ1c[m] - base; if (qlim > OWN) qlim = OWN;
                if (qlim <= 0) continue;
                float4 cb = s->scbox[m];
                if (cb.w + 1.0001f <= my_ymin1) continue;
                int ci = s->scidx[m];
#pragma unroll
                for (int q = 0; q < OWN; ++q) {
                    if (q < qlim && ((rv >> q) & 1u) && (base + q != ci)) {
                        float iw = fminf(cb.z, rx2[q]) - fmaxf(cb.x, rx1[q]) + 1.0f;
                        float ih = fminf(cb.w, ry2[q]) - fmaxf(cb.y, ry1[q]) + 1.0f;
                        if (iw > 0.0f && ih > 0.0f && iou_ge(iw * ih, rar[q]))
                            rv &= ~(1u << q);
                    }
                }
            }
            unsigned clr = oldrv & ~rv;
            if (clr) {
                unsigned long long m64 = (unsigned long long)clr << (base & 31);
                int wdw = base >> 5;
                unsigned lo = (unsigned)m64, hi = (unsigned)(m64 >> 32);
                if (lo) atomicAnd(&s->swords[wdw], ~lo);
                if (hi) atomicAnd(&s->swords[wdw + 1], ~hi);
            }
        }
        __syncthreads();                       // A: mask updates visible to next gather
    }

    // ---- output: first NPOST survivors in index order ----
    int cnt = __popc(rv);
    s->ssc[tid] = cnt;
    __syncthreads();
    for (int off = 1; off < NMS_NT; off <<= 1) {
        int add = (tid >= off) ? s->ssc[tid - off] : 0;
        __syncthreads();
        s->ssc[tid] += add;
        __syncthreads();
    }
    int pos = s->ssc[tid] - cnt;
#pragma unroll
    for (int q = 0; q < OWN; ++q) {
        if ((rv >> q) & 1u) {
            if (pos < NPOST) {
                float4 pp = g_props[(int)g_yv_b[base + q]];
                out[pos * 4 + 0] = pp.x;
                out[pos * 4 + 1] = pp.y;
                out[pos * 4 + 2] = pp.z;
                out[pos * 4 + 3] = pp.w;
            }
            ++pos;
        }
    }
}

extern "C" void kernel_launch(void* const* d_in, const int* in_sizes, int n_in,
                              void* d_out, int out_size)
{
    const float*  scores = (const float*)d_in[0];
    const float4* deltas = (const float4*)d_in[1];
    float* out = (float*)d_out;
    (void)in_sizes; (void)n_in; (void)out_size;

    void *p_ska, *p_skb, *p_sva, *p_svb, *p_yka, *p_ykb, *p_yva, *p_yvb, *p_tmp;
    cudaGetSymbolAddress(&p_ska, g_sk_a);
    cudaGetSymbolAddress(&p_skb, g_sk_b);
    cudaGetSymbolAddress(&p_sva, g_sv_a);
    cudaGetSymbolAddress(&p_svb, g_sv_b);
    cudaGetSymbolAddress(&p_yka, g_yk_a);
    cudaGetSymbolAddress(&p_ykb, g_yk_b);
    cudaGetSymbolAddress(&p_yva, g_yv_a);
    cudaGetSymbolAddress(&p_yvb, g_yv_b);
    cudaGetSymbolAddress(&p_tmp, g_cub_temp);

    k_score<<<(NBOX + 255) / 256, 256>>>(scores, deltas);

    size_t tb = sizeof(g_cub_temp);
    cub::DeviceRadixSort::SortPairs(p_tmp, tb,
        (const unsigned*)p_ska, (unsigned*)p_skb,
        (const unsigned*)p_sva, (unsigned*)p_svb, NBOX);

    k_props<<<(KTOP + 255) / 256, 256>>>(deltas);

    tb = sizeof(g_cub_temp);
    cub::DeviceRadixSort::SortPairs(p_tmp, tb,
        (const unsigned*)p_yka, (unsigned*)p_ykb,
        (const unsigned*)p_yva, (unsigned*)p_yvb, KTOP);

    size_t smem = sizeof(SmemNMS);
    cudaFuncSetAttribute(k_nms, cudaFuncAttributeMaxDynamicSharedMemorySize, (int)smem);
    k_nms<<<1, NMS_NT, smem>>>(out);
}